// round 2
// baseline (speedup 1.0000x reference)
#include <cuda_runtime.h>
#include <cuda_bf16.h>
#include <cstdint>

// Fused: out = leaky( [x_up, leaky(gather(x_down) @ W_lin + b_lin)] @ W_fus + b_fus )
// Shapes: B=4, N_down=16384, N_up=65536, C_down=256, C_up=128, C_out=128
// M_total = 262144 rows. Per CTA: 128 rows x 128 out-cols, tf32 mma.sync.
// NOTE: up_idx is int32 on device (JAX x64 disabled downgrades int64->int32).

#define BM 128
#define KC 64
#define SA_STRIDE 68    // A chunk  [128][KC]   pad -> bank = 4g+t (conflict-free)
#define SB_STRIDE 136   // B chunk  [KC][128]   pad -> bank = 8t+g (conflict-free)
#define SX_STRIDE 132   // x_lin    [128][128]  pad -> bank = 4g+t (conflict-free)

#define N_DOWN 16384
#define C_DOWN 256
#define C_UP   128
#define LOG2_NUP 16     // N_up = 65536

// smem (floats): sA 128*68=8704 | sB 64*136=8704 | sX 128*132=16896 | bias 256 | rows 128(int)
#define SMEM_FLOATS (BM*SA_STRIDE + KC*SB_STRIDE + BM*SX_STRIDE + 256)
#define SMEM_BYTES  (SMEM_FLOATS*4 + 128*4)

__device__ __forceinline__ float f2tf32f(float x) {
    unsigned y;
    asm("cvt.rna.tf32.f32 %0, %1;" : "=r"(y) : "f"(x));
    return __uint_as_float(y);
}

__device__ __forceinline__ float leaky(float v) {
    return fmaxf(v, 0.1f * v);
}

__device__ __forceinline__ void mma_tf32(float c[4], const unsigned a[4], const unsigned b[2]) {
    asm volatile("mma.sync.aligned.m16n8k8.row.col.f32.tf32.tf32.f32 "
                 "{%0,%1,%2,%3}, {%4,%5,%6,%7}, {%8,%9}, {%0,%1,%2,%3};"
                 : "+f"(c[0]), "+f"(c[1]), "+f"(c[2]), "+f"(c[3])
                 : "r"(a[0]), "r"(a[1]), "r"(a[2]), "r"(a[3]),
                   "r"(b[0]), "r"(b[1]));
}

// Compute one K-chunk of KC columns: acc += A[128 x KC] @ B[KC x 128]
// A fragments read from (Abase, Astride); B always from sB (already tf32).
__device__ __forceinline__ void compute_chunk(
    const float* __restrict__ Abase, int Astride,
    const float* __restrict__ sB,
    float acc[4][4][4], int wm, int wn, int g, int t)
{
#pragma unroll
    for (int kk = 0; kk < KC; kk += 8) {
        unsigned a[4][4];
#pragma unroll
        for (int mi = 0; mi < 4; mi++) {
            const float* ap = Abase + (wm * 64 + mi * 16 + g) * Astride + kk + t;
            a[mi][0] = __float_as_uint(ap[0]);
            a[mi][1] = __float_as_uint(ap[8 * Astride]);
            a[mi][2] = __float_as_uint(ap[4]);
            a[mi][3] = __float_as_uint(ap[8 * Astride + 4]);
        }
        unsigned bb[4][2];
#pragma unroll
        for (int ni = 0; ni < 4; ni++) {
            const float* bp = sB + (kk + t) * SB_STRIDE + wn * 32 + ni * 8 + g;
            bb[ni][0] = __float_as_uint(bp[0]);
            bb[ni][1] = __float_as_uint(bp[4 * SB_STRIDE]);
        }
#pragma unroll
        for (int mi = 0; mi < 4; mi++)
#pragma unroll
            for (int ni = 0; ni < 4; ni++)
                mma_tf32(acc[mi][ni], a[mi], bb[ni]);
    }
}

__global__ void __launch_bounds__(256, 1)
upsampling_fused_kernel(const float* __restrict__ x_down,
                        const float* __restrict__ x_up,
                        const int* __restrict__ up_idx,
                        const float* __restrict__ W_lin,
                        const float* __restrict__ b_lin,
                        const float* __restrict__ W_fus,
                        const float* __restrict__ b_fus,
                        float* __restrict__ out)
{
    extern __shared__ float sm[];
    float* sA    = sm;                           // [128][68]
    float* sB    = sA + BM * SA_STRIDE;          // [64][136]
    float* sX    = sB + KC * SB_STRIDE;          // [128][132]
    float* sBias = sX + BM * SX_STRIDE;          // [256]
    int*   sRow  = (int*)(sBias + 256);          // [128]

    const int tid  = threadIdx.x;
    const int lane = tid & 31;
    const int warp = tid >> 5;
    const int wm = warp >> 2;        // 0..1  (M 64-row halves)
    const int wn = warp & 3;         // 0..3  (N 32-col quarters)
    const int g  = lane >> 2;        // group id 0..7
    const int t  = lane & 3;         // thread-in-group 0..3

    const long long m0 = (long long)blockIdx.x * BM;
    const int bidx = (int)(m0 >> LOG2_NUP);

    if (tid < 128) {
        long long m = m0 + tid;
        int idx = up_idx[m];
        idx = max(0, min(idx, N_DOWN - 1));       // defensive clamp
        sRow[tid]        = bidx * N_DOWN + idx;   // gathered row in x_down
        sBias[tid]       = b_lin[tid];
        sBias[128 + tid] = b_fus[tid];
    }

    float acc[4][4][4];
#pragma unroll
    for (int mi = 0; mi < 4; mi++)
#pragma unroll
        for (int ni = 0; ni < 4; ni++)
#pragma unroll
            for (int q = 0; q < 4; q++) acc[mi][ni][q] = 0.0f;

    __syncthreads();   // sRow / sBias ready

    // ================= GEMM 1: gather(x_down)[128x256] @ W_lin[256x128] =================
    for (int kc = 0; kc < C_DOWN; kc += KC) {
        if (kc != 0) __syncthreads();   // prior compute done before overwrite
        // A chunk: gathered rows, 128 x 64, tf32-converted
#pragma unroll
        for (int i = 0; i < 8; i++) {
            int linear = tid + i * 256;
            int row = linear >> 4;          // 16 float4 per row
            int f4  = linear & 15;
            float4 v = *(const float4*)(x_down + (size_t)sRow[row] * C_DOWN + kc + f4 * 4);
            float4 w = make_float4(f2tf32f(v.x), f2tf32f(v.y), f2tf32f(v.z), f2tf32f(v.w));
            *(float4*)(sA + row * SA_STRIDE + f4 * 4) = w;
        }
        // B chunk: W_lin[kc:kc+64][0:128]
#pragma unroll
        for (int i = 0; i < 8; i++) {
            int linear = tid + i * 256;
            int row = linear >> 5;          // 32 float4 per row
            int f4  = linear & 31;
            float4 v = *(const float4*)(W_lin + (size_t)(kc + row) * C_UP + f4 * 4);
            float4 w = make_float4(f2tf32f(v.x), f2tf32f(v.y), f2tf32f(v.z), f2tf32f(v.w));
            *(float4*)(sB + row * SB_STRIDE + f4 * 4) = w;
        }
        __syncthreads();
        compute_chunk(sA, SA_STRIDE, sB, acc, wm, wn, g, t);
    }
    __syncthreads();

    // Epilogue 1: bias + leaky -> sX (tf32), then reuse acc for GEMM 2
#pragma unroll
    for (int mi = 0; mi < 4; mi++) {
        int r0 = wm * 64 + mi * 16 + g;
#pragma unroll
        for (int ni = 0; ni < 4; ni++) {
            int c = wn * 32 + ni * 8 + 2 * t;
            float bz0 = sBias[c], bz1 = sBias[c + 1];
            sX[r0 * SX_STRIDE + c]           = f2tf32f(leaky(acc[mi][ni][0] + bz0));
            sX[r0 * SX_STRIDE + c + 1]       = f2tf32f(leaky(acc[mi][ni][1] + bz1));
            sX[(r0 + 8) * SX_STRIDE + c]     = f2tf32f(leaky(acc[mi][ni][2] + bz0));
            sX[(r0 + 8) * SX_STRIDE + c + 1] = f2tf32f(leaky(acc[mi][ni][3] + bz1));
            acc[mi][ni][0] = acc[mi][ni][1] = acc[mi][ni][2] = acc[mi][ni][3] = 0.0f;
        }
    }

    // ================= GEMM 2: [x_up | x_lin][128x256] @ W_fus[256x128] =================
    for (int kc = 0; kc < 2 * C_UP; kc += KC) {
        __syncthreads();   // prior compute / epilogue-1 writes done
        const bool fromUp = (kc < C_UP);
        if (fromUp) {
            // A chunk from x_up (contiguous rows m0..m0+127, cols kc..kc+63)
#pragma unroll
            for (int i = 0; i < 8; i++) {
                int linear = tid + i * 256;
                int row = linear >> 4;
                int f4  = linear & 15;
                float4 v = *(const float4*)(x_up + (size_t)(m0 + row) * C_UP + kc + f4 * 4);
                float4 w = make_float4(f2tf32f(v.x), f2tf32f(v.y), f2tf32f(v.z), f2tf32f(v.w));
                *(float4*)(sA + row * SA_STRIDE + f4 * 4) = w;
            }
        }
        // B chunk: W_fus[kc:kc+64][0:128]
#pragma unroll
        for (int i = 0; i < 8; i++) {
            int linear = tid + i * 256;
            int row = linear >> 5;
            int f4  = linear & 31;
            float4 v = *(const float4*)(W_fus + (size_t)(kc + row) * C_UP + f4 * 4);
            float4 w = make_float4(f2tf32f(v.x), f2tf32f(v.y), f2tf32f(v.z), f2tf32f(v.w));
            *(float4*)(sB + row * SB_STRIDE + f4 * 4) = w;
        }
        __syncthreads();
        if (fromUp)
            compute_chunk(sA, SA_STRIDE, sB, acc, wm, wn, g, t);
        else
            compute_chunk(sX + (kc - C_UP), SX_STRIDE, sB, acc, wm, wn, g, t);
    }

    // Epilogue 2: bias + leaky -> out (fp32), float2 stores
#pragma unroll
    for (int mi = 0; mi < 4; mi++) {
        int r0 = wm * 64 + mi * 16 + g;
#pragma unroll
        for (int ni = 0; ni < 4; ni++) {
            int c = wn * 32 + ni * 8 + 2 * t;
            float bz0 = sBias[128 + c], bz1 = sBias[129 + c];
            float2 v0, v1;
            v0.x = leaky(acc[mi][ni][0] + bz0);
            v0.y = leaky(acc[mi][ni][1] + bz1);
            v1.x = leaky(acc[mi][ni][2] + bz0);
            v1.y = leaky(acc[mi][ni][3] + bz1);
            *(float2*)(out + (size_t)(m0 + r0) * C_UP + c)     = v0;
            *(float2*)(out + (size_t)(m0 + r0 + 8) * C_UP + c) = v1;
        }
    }
}

extern "C" void kernel_launch(void* const* d_in, const int* in_sizes, int n_in,
                              void* d_out, int out_size)
{
    const float* x_down = (const float*)d_in[0];
    const float* x_up   = (const float*)d_in[1];
    const int*   up_idx = (const int*)d_in[2];
    const float* W_lin  = (const float*)d_in[3];
    const float* b_lin  = (const float*)d_in[4];
    const float* W_fus  = (const float*)d_in[5];
    const float* b_fus  = (const float*)d_in[6];
    float*       out    = (float*)d_out;

    const int M_total = in_sizes[2];          // 262144 rows (up_idx count)
    const int grid = M_total / BM;            // 2048 CTAs

    static bool attr_set = false;
    if (!attr_set) {
        cudaFuncSetAttribute(upsampling_fused_kernel,
                             cudaFuncAttributeMaxDynamicSharedMemorySize, SMEM_BYTES);
        attr_set = true;
    }

    upsampling_fused_kernel<<<grid, 256, SMEM_BYTES>>>(
        x_down, x_up, up_idx, W_lin, b_lin, W_fus, b_fus, out);
}

// round 3
// speedup vs baseline: 1.6152x; 1.6152x over previous
#include <cuda_runtime.h>
#include <cuda_bf16.h>
#include <cstdint>

// Fused: out = leaky( [x_up, leaky(gather(x_down) @ W_lin + b_lin)] @ W_fus + b_fus )
// B=4, N_down=16384, N_up=65536, C_down=256, C_up=128, C_out=128. M=262144.
// Per CTA: 128 rows x 128 cols. tf32 mma.sync, cp.async double-buffered chunks.
// up_idx is int32 on device (JAX x64-disabled downgrade).

#define BM 128
#define KC 64
#define SA_STRIDE 68    // A chunk [128][64] pad -> conflict-free frags, 272B row (16B-mult)
#define SB_STRIDE 136   // B chunk [64][128] pad -> conflict-free frags, 544B row
#define SX_STRIDE 132   // x_lin   [128][128] pad -> conflict-free frags

#define N_DOWN 16384
#define C_DOWN 256
#define C_UP   128
#define LOG2_NUP 16

// floats: sA 2*128*68 | sB 2*64*136 | sX 128*132 | bias 256 ; + sRow 128 ints
#define SMEM_FLOATS (2*BM*SA_STRIDE + 2*KC*SB_STRIDE + BM*SX_STRIDE + 256)
#define SMEM_BYTES  (SMEM_FLOATS*4 + 128*4)

__device__ __forceinline__ unsigned f2tf32u(float x) {
    unsigned y;
    asm("cvt.rna.tf32.f32 %0, %1;" : "=r"(y) : "f"(x));
    return y;
}

__device__ __forceinline__ float leaky(float v) { return fmaxf(v, 0.1f * v); }

__device__ __forceinline__ void cp16(uint32_t sdst, const void* gsrc) {
    asm volatile("cp.async.cg.shared.global [%0], [%1], 16;" :: "r"(sdst), "l"(gsrc));
}
__device__ __forceinline__ void cp_commit() { asm volatile("cp.async.commit_group;"); }

__device__ __forceinline__ void mma_tf32(float c[4], const unsigned a[4], const unsigned b[2]) {
    asm volatile("mma.sync.aligned.m16n8k8.row.col.f32.tf32.tf32.f32 "
                 "{%0,%1,%2,%3}, {%4,%5,%6,%7}, {%8,%9}, {%0,%1,%2,%3};"
                 : "+f"(c[0]), "+f"(c[1]), "+f"(c[2]), "+f"(c[3])
                 : "r"(a[0]), "r"(a[1]), "r"(a[2]), "r"(a[3]),
                   "r"(b[0]), "r"(b[1]));
}

// acc += A[128 x 64] @ B[64 x 128]; raw fp32 in smem, cvt.rna at fragment load.
__device__ __forceinline__ void compute_chunk(
    const float* __restrict__ Abase, int Astride,
    const float* __restrict__ sB,
    float acc[4][4][4], int wm, int wn, int g, int t)
{
#pragma unroll
    for (int kk = 0; kk < KC; kk += 8) {
        unsigned a[4][4];
#pragma unroll
        for (int mi = 0; mi < 4; mi++) {
            const float* ap = Abase + (wm * 64 + mi * 16 + g) * Astride + kk + t;
            a[mi][0] = f2tf32u(ap[0]);
            a[mi][1] = f2tf32u(ap[8 * Astride]);
            a[mi][2] = f2tf32u(ap[4]);
            a[mi][3] = f2tf32u(ap[8 * Astride + 4]);
        }
        unsigned bb[4][2];
#pragma unroll
        for (int ni = 0; ni < 4; ni++) {
            const float* bp = sB + (kk + t) * SB_STRIDE + wn * 32 + ni * 8 + g;
            bb[ni][0] = f2tf32u(bp[0]);
            bb[ni][1] = f2tf32u(bp[4 * SB_STRIDE]);
        }
#pragma unroll
        for (int mi = 0; mi < 4; mi++)
#pragma unroll
            for (int ni = 0; ni < 4; ni++)
                mma_tf32(acc[mi][ni], a[mi], bb[ni]);
    }
}

// Issue cp.async for chunk c (0..7) into buffer (c&1). One commit per chunk by caller.
__device__ __forceinline__ void issue_chunk(
    int c, float* sA, float* sB,
    const float* __restrict__ x_down, const float* __restrict__ x_up,
    const float* __restrict__ W_lin, const float* __restrict__ W_fus,
    const int* __restrict__ sRow, long long m0, int tid)
{
    float* sAbuf = sA + (c & 1) * BM * SA_STRIDE;
    float* sBbuf = sB + (c & 1) * KC * SB_STRIDE;

    if (c < 4) {
        int kc = c * KC;
#pragma unroll
        for (int i = 0; i < 8; i++) {                 // A: gathered x_down rows
            int linear = tid + i * 256;
            int row = linear >> 4, f4 = linear & 15;
            const void* src = x_down + (size_t)sRow[row] * C_DOWN + kc + f4 * 4;
            cp16((uint32_t)__cvta_generic_to_shared(sAbuf + row * SA_STRIDE + f4 * 4), src);
        }
#pragma unroll
        for (int i = 0; i < 8; i++) {                 // B: W_lin rows kc..kc+63
            int linear = tid + i * 256;
            int row = linear >> 5, f4 = linear & 31;
            const void* src = W_lin + (size_t)(kc + row) * C_UP + f4 * 4;
            cp16((uint32_t)__cvta_generic_to_shared(sBbuf + row * SB_STRIDE + f4 * 4), src);
        }
    } else if (c < 6) {
        int kc = (c - 4) * KC;
#pragma unroll
        for (int i = 0; i < 8; i++) {                 // A: x_up contiguous rows
            int linear = tid + i * 256;
            int row = linear >> 4, f4 = linear & 15;
            const void* src = x_up + (size_t)(m0 + row) * C_UP + kc + f4 * 4;
            cp16((uint32_t)__cvta_generic_to_shared(sAbuf + row * SA_STRIDE + f4 * 4), src);
        }
#pragma unroll
        for (int i = 0; i < 8; i++) {                 // B: W_fus rows kc..kc+63
            int linear = tid + i * 256;
            int row = linear >> 5, f4 = linear & 31;
            const void* src = W_fus + (size_t)(kc + row) * C_UP + f4 * 4;
            cp16((uint32_t)__cvta_generic_to_shared(sBbuf + row * SB_STRIDE + f4 * 4), src);
        }
    } else {
        int kc = C_UP + (c - 6) * KC;                 // B only; A comes from sX
#pragma unroll
        for (int i = 0; i < 8; i++) {
            int linear = tid + i * 256;
            int row = linear >> 5, f4 = linear & 31;
            const void* src = W_fus + (size_t)(kc + row) * C_UP + f4 * 4;
            cp16((uint32_t)__cvta_generic_to_shared(sBbuf + row * SB_STRIDE + f4 * 4), src);
        }
    }
}

__global__ void __launch_bounds__(256, 1)
upsampling_fused_kernel(const float* __restrict__ x_down,
                        const float* __restrict__ x_up,
                        const int* __restrict__ up_idx,
                        const float* __restrict__ W_lin,
                        const float* __restrict__ b_lin,
                        const float* __restrict__ W_fus,
                        const float* __restrict__ b_fus,
                        float* __restrict__ out)
{
    extern __shared__ float sm[];
    float* sA    = sm;                                 // 2 x [128][68]
    float* sB    = sA + 2 * BM * SA_STRIDE;            // 2 x [64][136]
    float* sX    = sB + 2 * KC * SB_STRIDE;            // [128][132]
    float* sBias = sX + BM * SX_STRIDE;                // [256]
    int*   sRow  = (int*)(sBias + 256);                // [128]

    const int tid  = threadIdx.x;
    const int lane = tid & 31;
    const int warp = tid >> 5;
    const int wm = warp >> 2;
    const int wn = warp & 3;
    const int g  = lane >> 2;
    const int t  = lane & 3;

    const long long m0 = (long long)blockIdx.x * BM;
    const int bidx = (int)(m0 >> LOG2_NUP);

    if (tid < 128) {
        int idx = up_idx[m0 + tid];
        idx = max(0, min(idx, N_DOWN - 1));
        sRow[tid]        = bidx * N_DOWN + idx;
        sBias[tid]       = b_lin[tid];
        sBias[128 + tid] = b_fus[tid];
    }

    float acc[4][4][4];
#pragma unroll
    for (int mi = 0; mi < 4; mi++)
#pragma unroll
        for (int ni = 0; ni < 4; ni++)
#pragma unroll
            for (int q = 0; q < 4; q++) acc[mi][ni][q] = 0.0f;

    __syncthreads();   // sRow ready before gather issue

    issue_chunk(0, sA, sB, x_down, x_up, W_lin, W_fus, sRow, m0, tid); cp_commit();
    issue_chunk(1, sA, sB, x_down, x_up, W_lin, W_fus, sRow, m0, tid); cp_commit();

#pragma unroll 1
    for (int c = 0; c < 8; c++) {
        if (c < 7) asm volatile("cp.async.wait_group 1;");
        else       asm volatile("cp.async.wait_group 0;");
        __syncthreads();                               // chunk c visible to all

        const float* Ab;
        int Astr;
        if (c < 6) { Ab = sA + (c & 1) * BM * SA_STRIDE; Astr = SA_STRIDE; }
        else       { Ab = sX + (c - 6) * KC;             Astr = SX_STRIDE; }
        compute_chunk(Ab, Astr, sB + (c & 1) * KC * SB_STRIDE, acc, wm, wn, g, t);

        if (c == 3) {
            // Epilogue 1: bias + leaky -> sX (raw fp32; cvt happens at fragment load)
#pragma unroll
            for (int mi = 0; mi < 4; mi++) {
                int r0 = wm * 64 + mi * 16 + g;
#pragma unroll
                for (int ni = 0; ni < 4; ni++) {
                    int cc = wn * 32 + ni * 8 + 2 * t;
                    float bz0 = sBias[cc], bz1 = sBias[cc + 1];
                    sX[r0 * SX_STRIDE + cc]           = leaky(acc[mi][ni][0] + bz0);
                    sX[r0 * SX_STRIDE + cc + 1]       = leaky(acc[mi][ni][1] + bz1);
                    sX[(r0 + 8) * SX_STRIDE + cc]     = leaky(acc[mi][ni][2] + bz0);
                    sX[(r0 + 8) * SX_STRIDE + cc + 1] = leaky(acc[mi][ni][3] + bz1);
                    acc[mi][ni][0] = acc[mi][ni][1] = acc[mi][ni][2] = acc[mi][ni][3] = 0.0f;
                }
            }
        }
        __syncthreads();                               // buffer (c&1) free; sX ready (c==3)
        if (c + 2 < 8) {
            issue_chunk(c + 2, sA, sB, x_down, x_up, W_lin, W_fus, sRow, m0, tid);
            cp_commit();
        }
    }

    // Epilogue 2: bias + leaky -> out
#pragma unroll
    for (int mi = 0; mi < 4; mi++) {
        int r0 = wm * 64 + mi * 16 + g;
#pragma unroll
        for (int ni = 0; ni < 4; ni++) {
            int cc = wn * 32 + ni * 8 + 2 * t;
            float bz0 = sBias[128 + cc], bz1 = sBias[129 + cc];
            float2 v0, v1;
            v0.x = leaky(acc[mi][ni][0] + bz0);
            v0.y = leaky(acc[mi][ni][1] + bz1);
            v1.x = leaky(acc[mi][ni][2] + bz0);
            v1.y = leaky(acc[mi][ni][3] + bz1);
            *(float2*)(out + (size_t)(m0 + r0) * C_UP + cc)     = v0;
            *(float2*)(out + (size_t)(m0 + r0 + 8) * C_UP + cc) = v1;
        }
    }
}

extern "C" void kernel_launch(void* const* d_in, const int* in_sizes, int n_in,
                              void* d_out, int out_size)
{
    const float* x_down = (const float*)d_in[0];
    const float* x_up   = (const float*)d_in[1];
    const int*   up_idx = (const int*)d_in[2];
    const float* W_lin  = (const float*)d_in[3];
    const float* b_lin  = (const float*)d_in[4];
    const float* W_fus  = (const float*)d_in[5];
    const float* b_fus  = (const float*)d_in[6];
    float*       out    = (float*)d_out;

    const int M_total = in_sizes[2];      // 262144
    const int grid = M_total / BM;        // 2048

    static bool attr_set = false;
    if (!attr_set) {
        cudaFuncSetAttribute(upsampling_fused_kernel,
                             cudaFuncAttributeMaxDynamicSharedMemorySize, SMEM_BYTES);
        attr_set = true;
    }

    upsampling_fused_kernel<<<grid, 256, SMEM_BYTES>>>(
        x_down, x_up, up_idx, W_lin, b_lin, W_fus, b_fus, out);
}

// round 12
// speedup vs baseline: 2.4713x; 1.5300x over previous
#include <cuda_runtime.h>
#include <cuda_fp16.h>
#include <cstdint>

// Fused: out = leaky( [x_up, leaky(gather(x_down) @ W_lin + b_lin)] @ W_fus + b_fus )
// B=4, N_down=16384, N_up=65536, C_down=256, C_up=128, C_out=128. M=262144.
// Per CTA: 128 rows x 128 cols. fp16 mma.sync.m16n8k16 (fp32 accum).
// A tiles: fp32 via cp.async (gather), converted to half at fragment load.
// B tiles: pre-transposed half [n][k] via cp.async. R3-proven unroll-1 pipeline.

#define BM 128
#define KC 64
#define N_DOWN 16384
#define C_DOWN 256
#define C_UP   128
#define LOG2_NUP 16

#define SA_STRIDE 72      // floats per A row (64 data + 8 pad): float2 frags conflict-free
#define B_STRH 72         // halves per B row (64 data + 8 pad): LDS.32 frags conflict-free
#define X_STRH 136        // halves per sX row (128 data + 8 pad)

// byte offsets in dynamic smem
#define SA_B(b) ((b) * (BM * SA_STRIDE * 4))               // 2 x 36864
#define SB_B(b) (2 * BM * SA_STRIDE * 4 + (b) * (BM * B_STRH * 2))  // 2 x 18432
#define SX_B    (2 * BM * SA_STRIDE * 4 + 2 * BM * B_STRH * 2)      // 110592
#define SBIAS_B (SX_B + BM * X_STRH * 2)                   // 145408
#define SROW_B  (SBIAS_B + 256 * 4)                        // 146432
#define SMEM_BYTES (SROW_B + 128 * 4)                      // 146944

__device__ __half g_WtLin[C_UP * C_DOWN];    // [n][k] half
__device__ __half g_WtFus[C_UP * 2 * C_UP];  // [n][k] half

__device__ __forceinline__ float leaky(float v) { return fmaxf(v, 0.1f * v); }

__device__ __forceinline__ unsigned pack2(float2 v) {
    unsigned r;
    asm("cvt.rn.f16x2.f32 %0, %1, %2;" : "=r"(r) : "f"(v.y), "f"(v.x));
    return r;
}
__device__ __forceinline__ void cp16(uint32_t sdst, const void* gsrc) {
    asm volatile("cp.async.cg.shared.global [%0], [%1], 16;" :: "r"(sdst), "l"(gsrc));
}
__device__ __forceinline__ void cp_commit() { asm volatile("cp.async.commit_group;"); }

__device__ __forceinline__ void mma_f16(float c[4], const unsigned a[4], const unsigned b[2]) {
    asm volatile("mma.sync.aligned.m16n8k16.row.col.f32.f16.f16.f32 "
                 "{%0,%1,%2,%3}, {%4,%5,%6,%7}, {%8,%9}, {%0,%1,%2,%3};"
                 : "+f"(c[0]), "+f"(c[1]), "+f"(c[2]), "+f"(c[3])
                 : "r"(a[0]), "r"(a[1]), "r"(a[2]), "r"(a[3]),
                   "r"(b[0]), "r"(b[1]));
}

// acc += A[128x64](fp32 smem) @ B[n][k](half smem)
__device__ __forceinline__ void compute_f32A(
    const float* __restrict__ Ab, const __half* __restrict__ Bb,
    float acc[4][4][4], int wm, int wn, int g, int t)
{
#pragma unroll
    for (int kk = 0; kk < KC; kk += 16) {
        unsigned a[4][4];
#pragma unroll
        for (int mi = 0; mi < 4; mi++) {
            const float* ap = Ab + (wm * 64 + mi * 16 + g) * SA_STRIDE + kk + 2 * t;
            a[mi][0] = pack2(*(const float2*)(ap));
            a[mi][1] = pack2(*(const float2*)(ap + 8 * SA_STRIDE));
            a[mi][2] = pack2(*(const float2*)(ap + 8));
            a[mi][3] = pack2(*(const float2*)(ap + 8 * SA_STRIDE + 8));
        }
        unsigned bb[4][2];
#pragma unroll
        for (int ni = 0; ni < 4; ni++) {
            const __half* bp = Bb + (wn * 32 + ni * 8 + g) * B_STRH + kk + 2 * t;
            bb[ni][0] = *(const unsigned*)(bp);
            bb[ni][1] = *(const unsigned*)(bp + 8);
        }
#pragma unroll
        for (int mi = 0; mi < 4; mi++)
#pragma unroll
            for (int ni = 0; ni < 4; ni++)
                mma_f16(acc[mi][ni], a[mi], bb[ni]);
    }
}

// acc += sX[128x64 half slice] @ B[n][k](half smem)
__device__ __forceinline__ void compute_h16A(
    const __half* __restrict__ Ab, const __half* __restrict__ Bb,
    float acc[4][4][4], int wm, int wn, int g, int t)
{
#pragma unroll
    for (int kk = 0; kk < KC; kk += 16) {
        unsigned a[4][4];
#pragma unroll
        for (int mi = 0; mi < 4; mi++) {
            const __half* ap = Ab + (wm * 64 + mi * 16 + g) * X_STRH + kk + 2 * t;
            a[mi][0] = *(const unsigned*)(ap);
            a[mi][1] = *(const unsigned*)(ap + 8 * X_STRH);
            a[mi][2] = *(const unsigned*)(ap + 8);
            a[mi][3] = *(const unsigned*)(ap + 8 * X_STRH + 8);
        }
        unsigned bb[4][2];
#pragma unroll
        for (int ni = 0; ni < 4; ni++) {
            const __half* bp = Bb + (wn * 32 + ni * 8 + g) * B_STRH + kk + 2 * t;
            bb[ni][0] = *(const unsigned*)(bp);
            bb[ni][1] = *(const unsigned*)(bp + 8);
        }
#pragma unroll
        for (int mi = 0; mi < 4; mi++)
#pragma unroll
            for (int ni = 0; ni < 4; ni++)
                mma_f16(acc[mi][ni], a[mi], bb[ni]);
    }
}

// cp.async chunk c into buffer (c&1). Chunks 0-3: gather A + WtLin. 4-5: x_up A + WtFus.
// 6-7: WtFus only (A = sX).
__device__ __forceinline__ void issue_chunk(
    int c, char* smc, uint32_t sbase,
    const float* __restrict__ x_down, const float* __restrict__ x_up,
    const int* __restrict__ sRow, long long m0, int tid)
{
    uint32_t ab = sbase + SA_B(c & 1);
    uint32_t bbase = sbase + SB_B(c & 1);

    if (c < 6) {
        int kc = (c < 4) ? c * KC : (c - 4) * KC;
#pragma unroll
        for (int i = 0; i < 8; i++) {               // A: 128 rows x 16 float4
            int lin = tid + i * 256;
            int row = lin >> 4, f4 = lin & 15;
            const float* src;
            if (c < 4) src = x_down + (size_t)sRow[row] * C_DOWN + kc + f4 * 4;
            else       src = x_up + (size_t)(m0 + row) * C_UP + kc + f4 * 4;
            cp16(ab + (uint32_t)(row * SA_STRIDE + f4 * 4) * 4, src);
        }
    }
    {
        const __half* W = (c < 4) ? g_WtLin : g_WtFus;
        int kt = (c < 4) ? C_DOWN : 2 * C_UP;
        int kc = (c < 4) ? c * KC : (c - 4) * KC;
#pragma unroll
        for (int i = 0; i < 4; i++) {               // B: 128 n-rows x 8 units of 8 halves
            int lin = tid + i * 256;
            int n = lin >> 3, u = lin & 7;
            cp16(bbase + (uint32_t)(n * B_STRH + u * 8) * 2,
                 W + (size_t)n * kt + kc + u * 8);
        }
    }
}

__global__ void prep_weights(const float* __restrict__ Wl, const float* __restrict__ Wf) {
    int i = blockIdx.x * 256 + threadIdx.x;       // 32768 threads
    if (i < C_DOWN * C_UP) {
        int k = i >> 7, n = i & 127;
        g_WtLin[n * C_DOWN + k]   = __float2half_rn(Wl[i]);
        g_WtFus[n * 2 * C_UP + k] = __float2half_rn(Wf[i]);
    }
}

__global__ void __launch_bounds__(256, 1)
upsampling_f16_kernel(const float* __restrict__ x_down,
                      const float* __restrict__ x_up,
                      const int* __restrict__ up_idx,
                      const float* __restrict__ b_lin,
                      const float* __restrict__ b_fus,
                      float* __restrict__ out)
{
    extern __shared__ __align__(16) char smc[];
    __half* sX   = (__half*)(smc + SX_B);
    float* sBias = (float*)(smc + SBIAS_B);
    int*   sRow  = (int*)(smc + SROW_B);
    uint32_t sbase;
    asm("{ .reg .u64 t; cvta.to.shared.u64 t, %1; cvt.u32.u64 %0, t; }" : "=r"(sbase) : "l"(smc));

    const int tid  = threadIdx.x;
    const int lane = tid & 31;
    const int warp = tid >> 5;
    const int wm = warp >> 2, wn = warp & 3;
    const int g = lane >> 2, t = lane & 3;

    const long long m0 = (long long)blockIdx.x * BM;
    const int bidx = (int)(m0 >> LOG2_NUP);

    if (tid < 128) {
        int idx = up_idx[m0 + tid];
        idx = max(0, min(idx, N_DOWN - 1));
        sRow[tid]        = bidx * N_DOWN + idx;
        sBias[tid]       = b_lin[tid];
        sBias[128 + tid] = b_fus[tid];
    }

    float acc[4][4][4];
#pragma unroll
    for (int mi = 0; mi < 4; mi++)
#pragma unroll
        for (int ni = 0; ni < 4; ni++)
#pragma unroll
            for (int q = 0; q < 4; q++) acc[mi][ni][q] = 0.0f;

    __syncthreads();   // sRow ready

    issue_chunk(0, smc, sbase, x_down, x_up, sRow, m0, tid); cp_commit();
    issue_chunk(1, smc, sbase, x_down, x_up, sRow, m0, tid); cp_commit();

#pragma unroll 1
    for (int c = 0; c < 8; c++) {
        if (c < 7) asm volatile("cp.async.wait_group 1;");
        else       asm volatile("cp.async.wait_group 0;");
        __syncthreads();                               // chunk c visible

        const __half* Bb = (const __half*)(smc + SB_B(c & 1));
        if (c < 6)
            compute_f32A((const float*)(smc + SA_B(c & 1)), Bb, acc, wm, wn, g, t);
        else
            compute_h16A(sX + (c - 6) * KC, Bb, acc, wm, wn, g, t);

        if (c == 3) {
            // Epilogue 1: bias + leaky -> sX (half), reset acc for GEMM2.
#pragma unroll
            for (int mi = 0; mi < 4; mi++) {
                int r0 = wm * 64 + mi * 16 + g;
#pragma unroll
                for (int ni = 0; ni < 4; ni++) {
                    int cc = wn * 32 + ni * 8 + 2 * t;
                    float bz0 = sBias[cc], bz1 = sBias[cc + 1];
                    float2 v0 = make_float2(leaky(acc[mi][ni][0] + bz0),
                                            leaky(acc[mi][ni][1] + bz1));
                    float2 v1 = make_float2(leaky(acc[mi][ni][2] + bz0),
                                            leaky(acc[mi][ni][3] + bz1));
                    *(unsigned*)(sX + r0 * X_STRH + cc)       = pack2(v0);
                    *(unsigned*)(sX + (r0 + 8) * X_STRH + cc) = pack2(v1);
                    acc[mi][ni][0] = acc[mi][ni][1] = acc[mi][ni][2] = acc[mi][ni][3] = 0.0f;
                }
            }
        }
        __syncthreads();                               // buffer (c&1) free; sX ready (c==3)
        if (c + 2 < 8) {
            issue_chunk(c + 2, smc, sbase, x_down, x_up, sRow, m0, tid);
            cp_commit();
        }
    }

    // Epilogue 2: bias + leaky -> out (fp32)
#pragma unroll
    for (int mi = 0; mi < 4; mi++) {
        int r0 = wm * 64 + mi * 16 + g;
#pragma unroll
        for (int ni = 0; ni < 4; ni++) {
            int cc = wn * 32 + ni * 8 + 2 * t;
            float bz0 = sBias[128 + cc], bz1 = sBias[129 + cc];
            float2 v0, v1;
            v0.x = leaky(acc[mi][ni][0] + bz0);
            v0.y = leaky(acc[mi][ni][1] + bz1);
            v1.x = leaky(acc[mi][ni][2] + bz0);
            v1.y = leaky(acc[mi][ni][3] + bz1);
            *(float2*)(out + (size_t)(m0 + r0) * C_UP + cc)     = v0;
            *(float2*)(out + (size_t)(m0 + r0 + 8) * C_UP + cc) = v1;
        }
    }
}

extern "C" void kernel_launch(void* const* d_in, const int* in_sizes, int n_in,
                              void* d_out, int out_size)
{
    const float* x_down = (const float*)d_in[0];
    const float* x_up   = (const float*)d_in[1];
    const int*   up_idx = (const int*)d_in[2];
    const float* W_lin  = (const float*)d_in[3];
    const float* b_lin  = (const float*)d_in[4];
    const float* W_fus  = (const float*)d_in[5];
    const float* b_fus  = (const float*)d_in[6];
    float*       out    = (float*)d_out;

    const int M_total = in_sizes[2];   // 262144
    const int grid = M_total / BM;     // 2048

    static bool attr_set = false;
    if (!attr_set) {
        cudaFuncSetAttribute(upsampling_f16_kernel,
                             cudaFuncAttributeMaxDynamicSharedMemorySize, SMEM_BYTES);
        attr_set = true;
    }

    prep_weights<<<128, 256>>>(W_lin, W_fus);
    upsampling_f16_kernel<<<grid, 256, SMEM_BYTES>>>(
        x_down, x_up, up_idx, b_lin, b_fus, out);
}